// round 1
// baseline (speedup 1.0000x reference)
#include <cuda_runtime.h>
#include <math.h>

#define Hh 4
#define Tt 1024
#define Dd 8192
#define SCALE 0.011048543456039806f  /* 1/sqrt(8192) */

// Scratch (static device arrays: allowed; no cudaMalloc anywhere)
__device__ float g_qr[(size_t)Hh * Tt * Dd];       // 128 MB rope'd query
__device__ float g_scores[(size_t)Hh * Tt * Tt];   // 16 MB masked scores

// ---------------------------------------------------------------------------
// Kernel 1: bug-faithful ROPE.
// v_rot comes from stack([-v[:,1::2], v[:,::2]], -1).reshape(B,H,T,D) where the
// slice is over the HEAD dim. Derived gather for output (h,t,d), pair m=d>>1:
//   q2 = t&1 ; d_src = q2*4096 + m ; t_src = (h&1)*512 + (t>>1)
//   d even (j=0): -query[(h&~1)|1][t_src][d_src]
//   d odd  (j=1): +query[(h&~1)  ][t_src][d_src]
// Both elements of a pair share freq (floor(d/2)*2 = 2m) and hence cos/sin.
// ---------------------------------------------------------------------------
__global__ void rope_kernel(const float* __restrict__ q) {
    long idx = (long)blockIdx.x * 256 + threadIdx.x;   // pair index, 2^24 total
    int m   = (int)(idx & (Dd / 2 - 1));               // 0..4095
    int row = (int)(idx >> 12);                        // h*T + t
    int t = row & (Tt - 1);
    int h = row >> 10;

    const float* qrow = q + ((long)row << 13);
    float v0 = qrow[2 * m];
    float v1 = qrow[2 * m + 1];

    int q2   = t & 1;
    int dsrc = (q2 << 12) + m;
    int tsrc = ((h & 1) << 9) + (t >> 1);
    int h2   = h >> 1;
    const float* base = q + ((long)(2 * h2) << 23);    // T*D = 2^23
    float rot0 = -base[(1L << 23) + (long)tsrc * Dd + dsrc]; // j=0 -> head 2*h2+1, negated
    float rot1 =  base[(long)tsrc * Dd + dsrc];              // j=1 -> head 2*h2

    // freq = 2^(-2m*16/8192) / (2*pi) = 2^(-m/256) / (2*pi)
    float freq = exp2f(-(float)m * (1.0f / 256.0f)) * 0.15915494309189535f;
    float ph = fmodf((float)t * freq, 1.0f);
    float c = cospif(2.0f * ph);
    float s = sinpif(2.0f * ph);

    float2 o;
    o.x = v0 * c + rot0 * s;
    o.y = v1 * c + rot1 * s;
    *(float2*)(g_qr + ((long)row << 13) + 2 * m) = o;
}

// ---------------------------------------------------------------------------
// Kernel 2: scores = mask_strict_lower( Qr Qr^T ) * SCALE, per head.
// 128x128 tile, BK=8, 256 threads, 8x8 microtile. Only lower-tri tiles launched
// (grid.x = 36). Diagonal tiles write zeros where s >= t; strictly-upper tiles
// are never written and never read downstream.
// ---------------------------------------------------------------------------
__global__ __launch_bounds__(256) void gemm1_scores() {
    const int h = blockIdx.y;
    int p = blockIdx.x;
    int bi = 0;
    while ((bi + 1) * (bi + 2) / 2 <= p) ++bi;
    int bj = p - bi * (bi + 1) / 2;

    const float* A = g_qr + ((long)h << 23) + (long)bi * 128 * Dd;
    const float* B = g_qr + ((long)h << 23) + (long)bj * 128 * Dd;
    float* C = g_scores + (long)h * Tt * Tt + (long)bi * 128 * Tt + bj * 128;

    __shared__ float As[8][140];
    __shared__ float Bs[8][140];

    int tid = threadIdx.x;
    int tx = tid & 15, ty = tid >> 4;
    int lrow = tid >> 1;
    int lseg = (tid & 1) << 2;
    const float* Ald = A + (long)lrow * Dd + lseg;
    const float* Bld = B + (long)lrow * Dd + lseg;

    float acc[8][8];
#pragma unroll
    for (int i = 0; i < 8; i++)
#pragma unroll
        for (int j = 0; j < 8; j++) acc[i][j] = 0.f;

    for (int k0 = 0; k0 < Dd; k0 += 8) {
        float4 a4 = *(const float4*)(Ald + k0);
        float4 b4 = *(const float4*)(Bld + k0);
        __syncthreads();
        As[lseg + 0][lrow] = a4.x; As[lseg + 1][lrow] = a4.y;
        As[lseg + 2][lrow] = a4.z; As[lseg + 3][lrow] = a4.w;
        Bs[lseg + 0][lrow] = b4.x; Bs[lseg + 1][lrow] = b4.y;
        Bs[lseg + 2][lrow] = b4.z; Bs[lseg + 3][lrow] = b4.w;
        __syncthreads();
#pragma unroll
        for (int k = 0; k < 8; k++) {
            float a[8], b[8];
            *(float4*)&a[0] = *(const float4*)&As[k][ty * 8];
            *(float4*)&a[4] = *(const float4*)&As[k][ty * 8 + 4];
            *(float4*)&b[0] = *(const float4*)&Bs[k][tx * 8];
            *(float4*)&b[4] = *(const float4*)&Bs[k][tx * 8 + 4];
#pragma unroll
            for (int i = 0; i < 8; i++)
#pragma unroll
                for (int j = 0; j < 8; j++) acc[i][j] += a[i] * b[j];
        }
    }

    int trow0 = bi * 128 + ty * 8;
    int scol0 = bj * 128 + tx * 8;
#pragma unroll
    for (int i = 0; i < 8; i++) {
        int t = trow0 + i;
#pragma unroll
        for (int j = 0; j < 8; j++) {
            int s = scol0 + j;
            C[(ty * 8 + i) * Tt + tx * 8 + j] = (s < t) ? acc[i][j] * SCALE : 0.f;
        }
    }
}

// ---------------------------------------------------------------------------
// Kernel 3: out = scores @ V, causal K bound per t-row-tile: K = (bi+1)*128.
// ---------------------------------------------------------------------------
__global__ __launch_bounds__(256) void gemm2_out(const float* __restrict__ V,
                                                 float* __restrict__ O) {
    const int h  = blockIdx.z;
    const int bi = blockIdx.y;  // t tile 0..7
    const int bn = blockIdx.x;  // d tile 0..63
    const int Kmax = (bi + 1) * 128;

    const float* A = g_scores + (long)h * Tt * Tt + (long)bi * 128 * Tt;
    const float* B = V + ((long)h << 23) + bn * 128;
    float* C = O + ((long)h << 23) + (long)bi * 128 * Dd + bn * 128;

    __shared__ float As[8][140];
    __shared__ float Bs[8][128];

    int tid = threadIdx.x;
    int tx = tid & 15, ty = tid >> 4;
    int lrow = tid >> 1;
    int lseg = (tid & 1) << 2;
    int brow = tid >> 5;          // 0..7
    int bcol = (tid & 31) << 2;   // 0..124

    float acc[8][8];
#pragma unroll
    for (int i = 0; i < 8; i++)
#pragma unroll
        for (int j = 0; j < 8; j++) acc[i][j] = 0.f;

    for (int k0 = 0; k0 < Kmax; k0 += 8) {
        float4 a4 = *(const float4*)(A + (long)lrow * Tt + k0 + lseg);
        float4 b4 = *(const float4*)(B + (long)(k0 + brow) * Dd + bcol);
        __syncthreads();
        As[lseg + 0][lrow] = a4.x; As[lseg + 1][lrow] = a4.y;
        As[lseg + 2][lrow] = a4.z; As[lseg + 3][lrow] = a4.w;
        *(float4*)&Bs[brow][bcol] = b4;
        __syncthreads();
#pragma unroll
        for (int k = 0; k < 8; k++) {
            float a[8], b[8];
            *(float4*)&a[0] = *(const float4*)&As[k][ty * 8];
            *(float4*)&a[4] = *(const float4*)&As[k][ty * 8 + 4];
            *(float4*)&b[0] = *(const float4*)&Bs[k][tx * 8];
            *(float4*)&b[4] = *(const float4*)&Bs[k][tx * 8 + 4];
#pragma unroll
            for (int i = 0; i < 8; i++)
#pragma unroll
                for (int j = 0; j < 8; j++) acc[i][j] += a[i] * b[j];
        }
    }

#pragma unroll
    for (int i = 0; i < 8; i++) {
        float4 o0 = make_float4(acc[i][0], acc[i][1], acc[i][2], acc[i][3]);
        float4 o1 = make_float4(acc[i][4], acc[i][5], acc[i][6], acc[i][7]);
        *(float4*)(C + (long)(ty * 8 + i) * Dd + tx * 8) = o0;
        *(float4*)(C + (long)(ty * 8 + i) * Dd + tx * 8 + 4) = o1;
    }
}

extern "C" void kernel_launch(void* const* d_in, const int* in_sizes, int n_in,
                              void* d_out, int out_size) {
    (void)in_sizes; (void)n_in; (void)out_size;
    const float* query = (const float*)d_in[0];
    const float* value = (const float*)d_in[1];
    float* out = (float*)d_out;

    rope_kernel<<<65536, 256>>>(query);

    dim3 g1(36, Hh);
    gemm1_scores<<<g1, 256>>>();

    dim3 g2(Dd / 128, Tt / 128, Hh);
    gemm2_out<<<g2, 256>>>(value, out);
}

// round 3
// speedup vs baseline: 3.4646x; 3.4646x over previous
#include <cuda_runtime.h>
#include <cuda_fp16.h>
#include <cstdint>
#include <math.h>

#define Hh 4
#define Tt 1024
#define Dd 8192
#define SCALE 0.011048543456039806f  /* 1/sqrt(8192) */

// ---------------- scratch (static device arrays; no allocation) -------------
__device__ __half g_qhi[(size_t)Hh * Tt * Dd];   // 64 MB
__device__ __half g_qlo[(size_t)Hh * Tt * Dd];   // 64 MB
__device__ __half g_vthi[(size_t)Hh * Dd * Tt];  // 64 MB  V^T [h][d][s]
__device__ __half g_vtlo[(size_t)Hh * Dd * Tt];  // 64 MB
__device__ __half g_shi[(size_t)Hh * Tt * Tt];   // 8 MB   scores hi
__device__ __half g_slo[(size_t)Hh * Tt * Tt];   // 8 MB   scores lo

// ---------------- helpers (base-arch PTX only: cp.async/ldmatrix/mma.sync) --
__device__ __forceinline__ uint32_t smem_u32(const void* p) {
    uint32_t a;
    asm("{ .reg .u64 t; cvta.to.shared.u64 t, %1; cvt.u32.u64 %0, t; }" : "=r"(a) : "l"(p));
    return a;
}
__device__ __forceinline__ void cp16(uint32_t dst, const void* src) {
    asm volatile("cp.async.cg.shared.global [%0], [%1], 16;" :: "r"(dst), "l"(src) : "memory");
}
#define CP_COMMIT asm volatile("cp.async.commit_group;" ::: "memory")
#define CP_WAIT1  asm volatile("cp.async.wait_group 1;" ::: "memory")

__device__ __forceinline__ void ldsm4(uint32_t& r0, uint32_t& r1, uint32_t& r2, uint32_t& r3,
                                      uint32_t a) {
    asm volatile("ldmatrix.sync.aligned.m8n8.x4.shared.b16 {%0,%1,%2,%3}, [%4];"
                 : "=r"(r0), "=r"(r1), "=r"(r2), "=r"(r3) : "r"(a));
}
__device__ __forceinline__ void mma16816(float* c,
                                         uint32_t a0, uint32_t a1, uint32_t a2, uint32_t a3,
                                         uint32_t b0, uint32_t b1) {
    asm volatile(
        "mma.sync.aligned.m16n8k16.row.col.f32.f16.f16.f32 "
        "{%0,%1,%2,%3},{%4,%5,%6,%7},{%8,%9},{%0,%1,%2,%3};"
        : "+f"(c[0]), "+f"(c[1]), "+f"(c[2]), "+f"(c[3])
        : "r"(a0), "r"(a1), "r"(a2), "r"(a3), "r"(b0), "r"(b1));
}

// 128B rows, SW128-style XOR swizzle: conflict-free ldmatrix + cp.async stores
#define SWZ(row, cb) ((row) * 128 + ((cb) ^ (((row) & 7) << 4)))

#define STAGE_BYTES 65536   /* Ahi 16K | Alo 16K | Bhi 16K | Blo 16K */
#define OPER_BYTES  16384

// ---------------------------------------------------------------------------
// Kernel 1: bug-faithful ROPE -> fp16 hi/lo split
// ---------------------------------------------------------------------------
__global__ void rope_kernel(const float* __restrict__ q) {
    long idx = (long)blockIdx.x * 256 + threadIdx.x;   // pair index
    int m   = (int)(idx & (Dd / 2 - 1));
    int row = (int)(idx >> 12);
    int t = row & (Tt - 1);
    int h = row >> 10;

    const float* qrow = q + ((long)row << 13);
    float v0 = qrow[2 * m];
    float v1 = qrow[2 * m + 1];

    int q2   = t & 1;
    int dsrc = (q2 << 12) + m;
    int tsrc = ((h & 1) << 9) + (t >> 1);
    int h2   = h >> 1;
    const float* base = q + ((long)(2 * h2) << 23);
    float rot0 = -base[(1L << 23) + (long)tsrc * Dd + dsrc];
    float rot1 =  base[(long)tsrc * Dd + dsrc];

    float freq = exp2f(-(float)m * (1.0f / 256.0f)) * 0.15915494309189535f;
    float ph = fmodf((float)t * freq, 1.0f);
    float c = cospif(2.0f * ph);
    float s = sinpif(2.0f * ph);

    float o0 = v0 * c + rot0 * s;
    float o1 = v1 * c + rot1 * s;

    __half h0 = __float2half_rn(o0);
    __half h1 = __float2half_rn(o1);
    __half l0 = __float2half_rn(o0 - __half2float(h0));
    __half l1 = __float2half_rn(o1 - __half2float(h1));

    long off = ((long)row << 13) + 2 * m;
    *(__half2*)(g_qhi + off) = __halves2half2(h0, h1);
    *(__half2*)(g_qlo + off) = __halves2half2(l0, l1);
}

// ---------------------------------------------------------------------------
// Kernel 2: V transpose [h][s][d] fp32 -> V^T [h][d][s] fp16 hi/lo
// ---------------------------------------------------------------------------
__global__ __launch_bounds__(256) void transpose_v(const float* __restrict__ V) {
    __shared__ float tile[32][33];
    int h = blockIdx.z;
    int d0 = blockIdx.x * 32, s0 = blockIdx.y * 32;
    int lx = threadIdx.x & 31, ly = threadIdx.x >> 5;
    const float* src = V + ((long)h << 23);
#pragma unroll
    for (int r = 0; r < 4; r++)
        tile[ly + r * 8][lx] = src[(long)(s0 + ly + r * 8) * Dd + d0 + lx];
    __syncthreads();
    long ob = ((long)h << 23);
#pragma unroll
    for (int r = 0; r < 4; r++) {
        int d = d0 + ly + r * 8;
        float v = tile[lx][ly + r * 8];
        __half hv = __float2half_rn(v);
        g_vthi[ob + (long)d * Tt + s0 + lx] = hv;
        g_vtlo[ob + (long)d * Tt + s0 + lx] = __float2half_rn(v - __half2float(hv));
    }
}

// ---------------------------------------------------------------------------
// GEMM core: CTA tile 128x128, BK=64, 8 warps of 32x64, fp16x3 split on HMMA.
// A [128 rows][K] K-major (ld=lda), B [128 n-rows][K] K-major (ld=ldb).
// ---------------------------------------------------------------------------
__device__ __forceinline__ void ld_tile(uint32_t sbase, const __half* g, long ld, int tid) {
#pragma unroll
    for (int i = 0; i < 4; i++) {
        int cid = i * 256 + tid;            // 0..1023
        int row = cid >> 3;
        int cb  = (cid & 7) << 4;           // byte col 0..112
        cp16(sbase + SWZ(row, cb), g + (long)row * ld + (cb >> 1));
    }
}

__device__ __forceinline__ void gemm_run(
    const __half* __restrict__ Ah, const __half* __restrict__ Al, long lda,
    const __half* __restrict__ Bh, const __half* __restrict__ Bl, long ldb,
    int nch, uint32_t s0, int tid, float acc[2][8][4])
{
    const int lane = tid & 31, wid = tid >> 5;
    const int wm = (wid & 3) * 32, wn = (wid >> 2) * 64;

    // prologue: fill both stages
#pragma unroll
    for (int s = 0; s < 2; s++) {
        uint32_t sb = s0 + s * STAGE_BYTES;
        ld_tile(sb,                  Ah + s * 64, lda, tid);
        ld_tile(sb + OPER_BYTES,     Al + s * 64, lda, tid);
        ld_tile(sb + 2 * OPER_BYTES, Bh + s * 64, ldb, tid);
        ld_tile(sb + 3 * OPER_BYTES, Bl + s * 64, ldb, tid);
        CP_COMMIT;
    }

    const int arow = lane & 15;                         // + wm + mb*16
    const int acb  = (lane >> 4) << 4;
    const int brow = (lane & 7) + ((lane >> 4) << 3);   // + wn + nb*16
    const int bcb  = ((lane >> 3) & 1) << 4;

    for (int kc = 0; kc < nch; kc++) {
        CP_WAIT1;
        __syncthreads();
        uint32_t sb = s0 + (kc & 1) * STAGE_BYTES;
#pragma unroll
        for (int kb = 0; kb < 4; kb++) {
            uint32_t a_h[2][4], a_l[2][4];
            int cbA = kb * 32 + acb;
#pragma unroll
            for (int mb = 0; mb < 2; mb++) {
                int r = wm + mb * 16 + arow;
                uint32_t off = SWZ(r, cbA);
                ldsm4(a_h[mb][0], a_h[mb][1], a_h[mb][2], a_h[mb][3], sb + off);
                ldsm4(a_l[mb][0], a_l[mb][1], a_l[mb][2], a_l[mb][3], sb + OPER_BYTES + off);
            }
            int cbB = kb * 32 + bcb;
#pragma unroll
            for (int nb = 0; nb < 4; nb++) {
                int r = wn + nb * 16 + brow;
                uint32_t off = SWZ(r, cbB);
                uint32_t bh0, bh1, bh2, bh3, bl0, bl1, bl2, bl3;
                ldsm4(bh0, bh1, bh2, bh3, sb + 2 * OPER_BYTES + off);
                ldsm4(bl0, bl1, bl2, bl3, sb + 3 * OPER_BYTES + off);
#pragma unroll
                for (int mb = 0; mb < 2; mb++) {
                    mma16816(acc[mb][2 * nb],     a_h[mb][0], a_h[mb][1], a_h[mb][2], a_h[mb][3], bh0, bh1);
                    mma16816(acc[mb][2 * nb + 1], a_h[mb][0], a_h[mb][1], a_h[mb][2], a_h[mb][3], bh2, bh3);
                    mma16816(acc[mb][2 * nb],     a_h[mb][0], a_h[mb][1], a_h[mb][2], a_h[mb][3], bl0, bl1);
                    mma16816(acc[mb][2 * nb + 1], a_h[mb][0], a_h[mb][1], a_h[mb][2], a_h[mb][3], bl2, bl3);
                    mma16816(acc[mb][2 * nb],     a_l[mb][0], a_l[mb][1], a_l[mb][2], a_l[mb][3], bh0, bh1);
                    mma16816(acc[mb][2 * nb + 1], a_l[mb][0], a_l[mb][1], a_l[mb][2], a_l[mb][3], bh2, bh3);
                }
            }
        }
        __syncthreads();
        if (kc + 2 < nch) {
            uint32_t sb2 = s0 + (kc & 1) * STAGE_BYTES;
            ld_tile(sb2,                  Ah + (kc + 2) * 64, lda, tid);
            ld_tile(sb2 + OPER_BYTES,     Al + (kc + 2) * 64, lda, tid);
            ld_tile(sb2 + 2 * OPER_BYTES, Bh + (kc + 2) * 64, ldb, tid);
            ld_tile(sb2 + 3 * OPER_BYTES, Bl + (kc + 2) * 64, ldb, tid);
        }
        CP_COMMIT;
    }
}

// ---------------------------------------------------------------------------
// Kernel 3: scores = mask_strict_lower(Qr Qr^T) * SCALE  (lower-tri tiles only)
// ---------------------------------------------------------------------------
__global__ __launch_bounds__(256, 1) void gemm1_scores() {
    extern __shared__ char dyn[];
    uint32_t s0 = smem_u32(dyn);
    int tid = threadIdx.x;
    int h = blockIdx.y;
    int p = blockIdx.x;
    int bi = 0;
    while ((bi + 1) * (bi + 2) / 2 <= p) ++bi;
    int bj = p - bi * (bi + 1) / 2;

    long qb = ((long)h << 23);
    const __half* Ah = g_qhi + qb + (long)bi * 128 * Dd;
    const __half* Al = g_qlo + qb + (long)bi * 128 * Dd;
    const __half* Bh = g_qhi + qb + (long)bj * 128 * Dd;
    const __half* Bl = g_qlo + qb + (long)bj * 128 * Dd;

    float acc[2][8][4];
#pragma unroll
    for (int a = 0; a < 2; a++)
#pragma unroll
        for (int b = 0; b < 8; b++)
#pragma unroll
            for (int c = 0; c < 4; c++) acc[a][b][c] = 0.f;

    gemm_run(Ah, Al, Dd, Bh, Bl, Dd, Dd / 64, s0, tid, acc);

    const int lane = tid & 31, wid = tid >> 5;
    const int wm = (wid & 3) * 32, wn = (wid >> 2) * 64;
    int tr0 = bi * 128 + wm + (lane >> 2);
    int sc0 = bj * 128 + wn + (lane & 3) * 2;
    long hb = (long)h * Tt * Tt;
#pragma unroll
    for (int mb = 0; mb < 2; mb++) {
#pragma unroll
        for (int n8 = 0; n8 < 8; n8++) {
            int sc = sc0 + n8 * 8;
            float* c = acc[mb][n8];
#pragma unroll
            for (int rh = 0; rh < 2; rh++) {
                int rr = tr0 + mb * 16 + rh * 8;
                float v0 = (sc     < rr) ? c[rh * 2 + 0] * SCALE : 0.f;
                float v1 = (sc + 1 < rr) ? c[rh * 2 + 1] * SCALE : 0.f;
                __half h0 = __float2half_rn(v0);
                __half h1 = __float2half_rn(v1);
                __half l0 = __float2half_rn(v0 - __half2float(h0));
                __half l1 = __float2half_rn(v1 - __half2float(h1));
                long o = hb + (long)rr * Tt + sc;
                *(__half2*)(g_shi + o) = __halves2half2(h0, h1);
                *(__half2*)(g_slo + o) = __halves2half2(l0, l1);
            }
        }
    }
}

// ---------------------------------------------------------------------------
// Kernel 4: out = scores @ V^T^T  (A = scores split, B = V^T split), causal K
// ---------------------------------------------------------------------------
__global__ __launch_bounds__(256, 1) void gemm2_out(float* __restrict__ O) {
    extern __shared__ char dyn[];
    uint32_t s0 = smem_u32(dyn);
    int tid = threadIdx.x;
    int bn = blockIdx.x;          // d tile 0..63
    int bi = 7 - blockIdx.y;      // t tile, big-K first
    int h  = blockIdx.z;

    const __half* Ah = g_shi + (long)h * Tt * Tt + (long)bi * 128 * Tt;
    const __half* Al = g_slo + (long)h * Tt * Tt + (long)bi * 128 * Tt;
    const __half* Bh = g_vthi + ((long)h << 23) + (long)bn * 128 * Tt;
    const __half* Bl = g_vtlo + ((long)h << 23) + (long)bn * 128 * Tt;

    float acc[2][8][4];
#pragma unroll
    for (int a = 0; a < 2; a++)
#pragma unroll
        for (int b = 0; b < 8; b++)
#pragma unroll
            for (int c = 0; c < 4; c++) acc[a][b][c] = 0.f;

    int nch = (bi + 1) * 2;   // K = (bi+1)*128
    gemm_run(Ah, Al, Tt, Bh, Bl, Tt, nch, s0, tid, acc);

    const int lane = tid & 31, wid = tid >> 5;
    const int wm = (wid & 3) * 32, wn = (wid >> 2) * 64;
    int tr0 = bi * 128 + wm + (lane >> 2);
    int dc0 = bn * 128 + wn + (lane & 3) * 2;
    long hb = ((long)h << 23);
#pragma unroll
    for (int mb = 0; mb < 2; mb++) {
#pragma unroll
        for (int n8 = 0; n8 < 8; n8++) {
            int dc = dc0 + n8 * 8;
            float* c = acc[mb][n8];
#pragma unroll
            for (int rh = 0; rh < 2; rh++) {
                int rr = tr0 + mb * 16 + rh * 8;
                *(float2*)(O + hb + (long)rr * Dd + dc) =
                    make_float2(c[rh * 2 + 0], c[rh * 2 + 1]);
            }
        }
    }
}

// ---------------------------------------------------------------------------
extern "C" void kernel_launch(void* const* d_in, const int* in_sizes, int n_in,
                              void* d_out, int out_size) {
    (void)in_sizes; (void)n_in; (void)out_size;
    const float* query = (const float*)d_in[0];
    const float* value = (const float*)d_in[1];
    float* out = (float*)d_out;

    const int SMEM_BYTES = 2 * STAGE_BYTES;  // 128 KB
    static int attr_done = 0;
    if (!attr_done) {
        cudaFuncSetAttribute(gemm1_scores, cudaFuncAttributeMaxDynamicSharedMemorySize, SMEM_BYTES);
        cudaFuncSetAttribute(gemm2_out,    cudaFuncAttributeMaxDynamicSharedMemorySize, SMEM_BYTES);
        attr_done = 1;
    }

    rope_kernel<<<65536, 256>>>(query);

    dim3 gt(Dd / 32, Tt / 32, Hh);
    transpose_v<<<gt, 256>>>(value);

    dim3 g1(36, Hh);
    gemm1_scores<<<g1, 256, SMEM_BYTES>>>();

    dim3 g2(Dd / 128, Tt / 128, Hh);
    gemm2_out<<<g2, 256, SMEM_BYTES>>>(out);
}

// round 4
// speedup vs baseline: 4.7023x; 1.3573x over previous
#include <cuda_runtime.h>
#include <cuda_fp16.h>
#include <cstdint>
#include <math.h>

#define Hh 4
#define Tt 1024
#define Dd 8192
#define SCALE 0.011048543456039806f  /* 1/sqrt(8192) */

// ---------------- scratch (static device arrays; no allocation) -------------
__device__ __half g_qhi[(size_t)Hh * Tt * Dd];   // 64 MB
__device__ __half g_qlo[(size_t)Hh * Tt * Dd];   // 64 MB
__device__ __half g_vthi[(size_t)Hh * Dd * Tt];  // 64 MB  V^T [h][d][s]
__device__ __half g_shi[(size_t)Hh * Tt * Tt];   // 8 MB   scores hi
__device__ __half g_slo[(size_t)Hh * Tt * Tt];   // 8 MB   scores lo

// ---------------- helpers (base-arch PTX only: cp.async/ldmatrix/mma.sync) --
__device__ __forceinline__ uint32_t smem_u32(const void* p) {
    uint32_t a;
    asm("{ .reg .u64 t; cvta.to.shared.u64 t, %1; cvt.u32.u64 %0, t; }" : "=r"(a) : "l"(p));
    return a;
}
__device__ __forceinline__ void cp16(uint32_t dst, const void* src) {
    asm volatile("cp.async.cg.shared.global [%0], [%1], 16;" :: "r"(dst), "l"(src) : "memory");
}
#define CP_COMMIT asm volatile("cp.async.commit_group;" ::: "memory")
#define CP_WAIT1  asm volatile("cp.async.wait_group 1;" ::: "memory")

__device__ __forceinline__ void ldsm4(uint32_t& r0, uint32_t& r1, uint32_t& r2, uint32_t& r3,
                                      uint32_t a) {
    asm volatile("ldmatrix.sync.aligned.m8n8.x4.shared.b16 {%0,%1,%2,%3}, [%4];"
                 : "=r"(r0), "=r"(r1), "=r"(r2), "=r"(r3) : "r"(a));
}
__device__ __forceinline__ void mma16816(float* c,
                                         uint32_t a0, uint32_t a1, uint32_t a2, uint32_t a3,
                                         uint32_t b0, uint32_t b1) {
    asm volatile(
        "mma.sync.aligned.m16n8k16.row.col.f32.f16.f16.f32 "
        "{%0,%1,%2,%3},{%4,%5,%6,%7},{%8,%9},{%0,%1,%2,%3};"
        : "+f"(c[0]), "+f"(c[1]), "+f"(c[2]), "+f"(c[3])
        : "r"(a0), "r"(a1), "r"(a2), "r"(a3), "r"(b0), "r"(b1));
}

// 128B rows (64 halves of K per sub-tile), XOR swizzle: conflict-free
#define SWZ(row, cb) ((row) * 128 + ((cb) ^ (((row) & 7) << 4)))

// BK = 128: each operand tile = 2 sub-tiles of [128 rows x 128B] = 32 KB
#define SUB_BYTES   16384
#define OPER_BYTES  32768
#define STAGE_BYTES 98304   /* Ah | Al | Bh */

// ---------------------------------------------------------------------------
// Kernel 1: bug-faithful ROPE -> fp16 hi/lo split
// ---------------------------------------------------------------------------
__global__ void rope_kernel(const float* __restrict__ q) {
    long idx = (long)blockIdx.x * 256 + threadIdx.x;   // pair index
    int m   = (int)(idx & (Dd / 2 - 1));
    int row = (int)(idx >> 12);
    int t = row & (Tt - 1);
    int h = row >> 10;

    const float* qrow = q + ((long)row << 13);
    float v0 = qrow[2 * m];
    float v1 = qrow[2 * m + 1];

    int q2   = t & 1;
    int dsrc = (q2 << 12) + m;
    int tsrc = ((h & 1) << 9) + (t >> 1);
    int h2   = h >> 1;
    const float* base = q + ((long)(2 * h2) << 23);
    float rot0 = -base[(1L << 23) + (long)tsrc * Dd + dsrc];
    float rot1 =  base[(long)tsrc * Dd + dsrc];

    float freq = exp2f(-(float)m * (1.0f / 256.0f)) * 0.15915494309189535f;
    float ph = fmodf((float)t * freq, 1.0f);
    float c = cospif(2.0f * ph);
    float s = sinpif(2.0f * ph);

    float o0 = v0 * c + rot0 * s;
    float o1 = v1 * c + rot1 * s;

    __half h0 = __float2half_rn(o0);
    __half h1 = __float2half_rn(o1);
    __half l0 = __float2half_rn(o0 - __half2float(h0));
    __half l1 = __float2half_rn(o1 - __half2float(h1));

    long off = ((long)row << 13) + 2 * m;
    *(__half2*)(g_qhi + off) = __halves2half2(h0, h1);
    *(__half2*)(g_qlo + off) = __halves2half2(l0, l1);
}

// ---------------------------------------------------------------------------
// Kernel 2: V transpose [h][s][d] fp32 -> V^T [h][d][s] fp16 (hi only)
// ---------------------------------------------------------------------------
__global__ __launch_bounds__(256) void transpose_v(const float* __restrict__ V) {
    __shared__ float tile[32][33];
    int h = blockIdx.z;
    int d0 = blockIdx.x * 32, s0 = blockIdx.y * 32;
    int lx = threadIdx.x & 31, ly = threadIdx.x >> 5;
    const float* src = V + ((long)h << 23);
#pragma unroll
    for (int r = 0; r < 4; r++)
        tile[ly + r * 8][lx] = src[(long)(s0 + ly + r * 8) * Dd + d0 + lx];
    __syncthreads();
    long ob = ((long)h << 23);
#pragma unroll
    for (int r = 0; r < 4; r++) {
        int d = d0 + ly + r * 8;
        g_vthi[ob + (long)d * Tt + s0 + lx] = __float2half_rn(tile[lx][ly + r * 8]);
    }
}

// ---------------------------------------------------------------------------
// GEMM core: CTA tile 128x128, BK=128, 8 warps of 32x64.
// C ~= (Ah + Al) * Bh  (2-term fp16 split)
// ---------------------------------------------------------------------------
__device__ __forceinline__ void ld_tile128(uint32_t sbase, const __half* g, long ld, int tid) {
#pragma unroll
    for (int i = 0; i < 8; i++) {
        int cid = i * 256 + tid;            // 0..2047
        int row = cid >> 4;
        int seg = cid & 15;                 // 16B segment within 256B row
        uint32_t off = (seg >> 3) * SUB_BYTES + SWZ(row, (seg & 7) << 4);
        cp16(sbase + off, g + (long)row * ld + seg * 8);
    }
}

__device__ __forceinline__ void gemm_run(
    const __half* __restrict__ Ah, const __half* __restrict__ Al, long lda,
    const __half* __restrict__ Bh, long ldb,
    int nch, uint32_t s0, int tid, float acc[2][8][4], bool mma_on)
{
    const int lane = tid & 31, wid = tid >> 5;
    const int wm = (wid & 3) * 32, wn = (wid >> 2) * 64;

    // prologue: fill up to 2 stages
#pragma unroll
    for (int s = 0; s < 2; s++) {
        if (s < nch) {
            uint32_t sb = s0 + s * STAGE_BYTES;
            ld_tile128(sb,                  Ah + s * 128, lda, tid);
            ld_tile128(sb + OPER_BYTES,     Al + s * 128, lda, tid);
            ld_tile128(sb + 2 * OPER_BYTES, Bh + s * 128, ldb, tid);
        }
        CP_COMMIT;
    }

    const int arow = lane & 15;
    const int acb  = (lane >> 4) << 4;
    const int brow = (lane & 7) + ((lane >> 4) << 3);
    const int bcb  = ((lane >> 3) & 1) << 4;

    for (int kc = 0; kc < nch; kc++) {
        CP_WAIT1;
        __syncthreads();
        uint32_t sb = s0 + (kc & 1) * STAGE_BYTES;
        if (mma_on) {
#pragma unroll
            for (int kb = 0; kb < 8; kb++) {
                uint32_t sub = (kb >> 2) * SUB_BYTES;
                int cbk = (kb & 3) * 32;
                uint32_t a_h[2][4], a_l[2][4];
#pragma unroll
                for (int mb = 0; mb < 2; mb++) {
                    int r = wm + mb * 16 + arow;
                    uint32_t off = sub + SWZ(r, cbk + acb);
                    ldsm4(a_h[mb][0], a_h[mb][1], a_h[mb][2], a_h[mb][3], sb + off);
                    ldsm4(a_l[mb][0], a_l[mb][1], a_l[mb][2], a_l[mb][3],
                          sb + OPER_BYTES + off);
                }
#pragma unroll
                for (int nb = 0; nb < 4; nb++) {
                    int r = wn + nb * 16 + brow;
                    uint32_t off = sub + SWZ(r, cbk + bcb);
                    uint32_t b0, b1, b2, b3;
                    ldsm4(b0, b1, b2, b3, sb + 2 * OPER_BYTES + off);
#pragma unroll
                    for (int mb = 0; mb < 2; mb++) {
                        mma16816(acc[mb][2 * nb],     a_h[mb][0], a_h[mb][1], a_h[mb][2], a_h[mb][3], b0, b1);
                        mma16816(acc[mb][2 * nb],     a_l[mb][0], a_l[mb][1], a_l[mb][2], a_l[mb][3], b0, b1);
                        mma16816(acc[mb][2 * nb + 1], a_h[mb][0], a_h[mb][1], a_h[mb][2], a_h[mb][3], b2, b3);
                        mma16816(acc[mb][2 * nb + 1], a_l[mb][0], a_l[mb][1], a_l[mb][2], a_l[mb][3], b2, b3);
                    }
                }
            }
        }
        __syncthreads();
        if (kc + 2 < nch) {
            uint32_t sb2 = s0 + (kc & 1) * STAGE_BYTES;
            ld_tile128(sb2,                  Ah + (kc + 2) * 128, lda, tid);
            ld_tile128(sb2 + OPER_BYTES,     Al + (kc + 2) * 128, lda, tid);
            ld_tile128(sb2 + 2 * OPER_BYTES, Bh + (kc + 2) * 128, ldb, tid);
        }
        CP_COMMIT;
    }
}

// ---------------------------------------------------------------------------
// Kernel 3: scores = mask_strict_lower(Qr Qr^T) * SCALE  (lower-tri tiles only)
// ---------------------------------------------------------------------------
__global__ __launch_bounds__(256, 1) void gemm1_scores() {
    extern __shared__ char dyn[];
    uint32_t s0 = smem_u32(dyn);
    int tid = threadIdx.x;
    int h = blockIdx.y;
    int p = blockIdx.x;
    int bi = 0;
    while ((bi + 1) * (bi + 2) / 2 <= p) ++bi;
    int bj = p - bi * (bi + 1) / 2;

    long qb = ((long)h << 23);
    const __half* Ah = g_qhi + qb + (long)bi * 128 * Dd;
    const __half* Al = g_qlo + qb + (long)bi * 128 * Dd;
    const __half* Bh = g_qhi + qb + (long)bj * 128 * Dd;

    float acc[2][8][4];
#pragma unroll
    for (int a = 0; a < 2; a++)
#pragma unroll
        for (int b = 0; b < 8; b++)
#pragma unroll
            for (int c = 0; c < 4; c++) acc[a][b][c] = 0.f;

    const int lane = tid & 31, wid = tid >> 5;
    const int wm = (wid & 3) * 32, wn = (wid >> 2) * 64;
    // warp sub-tile fully masked on diagonal tiles when all s-cols >= all t-rows
    bool mma_on = !(bi == bj && wn >= wm + 32);

    gemm_run(Ah, Al, Dd, Bh, Dd, Dd / 128, s0, tid, acc, mma_on);

    int tr0 = bi * 128 + wm + (lane >> 2);
    int sc0 = bj * 128 + wn + (lane & 3) * 2;
    long hb = (long)h * Tt * Tt;
#pragma unroll
    for (int mb = 0; mb < 2; mb++) {
#pragma unroll
        for (int n8 = 0; n8 < 8; n8++) {
            int sc = sc0 + n8 * 8;
            float* c = acc[mb][n8];
#pragma unroll
            for (int rh = 0; rh < 2; rh++) {
                int rr = tr0 + mb * 16 + rh * 8;
                float v0 = (sc     < rr) ? c[rh * 2 + 0] * SCALE : 0.f;
                float v1 = (sc + 1 < rr) ? c[rh * 2 + 1] * SCALE : 0.f;
                __half h0 = __float2half_rn(v0);
                __half h1 = __float2half_rn(v1);
                __half l0 = __float2half_rn(v0 - __half2float(h0));
                __half l1 = __float2half_rn(v1 - __half2float(h1));
                long o = hb + (long)rr * Tt + sc;
                *(__half2*)(g_shi + o) = __halves2half2(h0, h1);
                *(__half2*)(g_slo + o) = __halves2half2(l0, l1);
            }
        }
    }
}

// ---------------------------------------------------------------------------
// Kernel 4: out = scores @ V   (A = scores hi+lo, B = V^T hi), causal K
// ---------------------------------------------------------------------------
__global__ __launch_bounds__(256, 1) void gemm2_out(float* __restrict__ O) {
    extern __shared__ char dyn[];
    uint32_t s0 = smem_u32(dyn);
    int tid = threadIdx.x;
    int bn = blockIdx.x;          // d tile 0..63
    int bi = 7 - blockIdx.y;      // t tile, big-K first
    int h  = blockIdx.z;

    const __half* Ah = g_shi + (long)h * Tt * Tt + (long)bi * 128 * Tt;
    const __half* Al = g_slo + (long)h * Tt * Tt + (long)bi * 128 * Tt;
    const __half* Bh = g_vthi + ((long)h << 23) + (long)bn * 128 * Tt;

    float acc[2][8][4];
#pragma unroll
    for (int a = 0; a < 2; a++)
#pragma unroll
        for (int b = 0; b < 8; b++)
#pragma unroll
            for (int c = 0; c < 4; c++) acc[a][b][c] = 0.f;

    int nch = bi + 1;   // K = (bi+1)*128, chunks of 128
    gemm_run(Ah, Al, Tt, Bh, Tt, nch, s0, tid, acc, true);

    const int lane = tid & 31, wid = tid >> 5;
    const int wm = (wid & 3) * 32, wn = (wid >> 2) * 64;
    int tr0 = bi * 128 + wm + (lane >> 2);
    int dc0 = bn * 128 + wn + (lane & 3) * 2;
    long hb = ((long)h << 23);
#pragma unroll
    for (int mb = 0; mb < 2; mb++) {
#pragma unroll
        for (int n8 = 0; n8 < 8; n8++) {
            int dc = dc0 + n8 * 8;
            float* c = acc[mb][n8];
#pragma unroll
            for (int rh = 0; rh < 2; rh++) {
                int rr = tr0 + mb * 16 + rh * 8;
                *(float2*)(O + hb + (long)rr * Dd + dc) =
                    make_float2(c[rh * 2 + 0], c[rh * 2 + 1]);
            }
        }
    }
}

// ---------------------------------------------------------------------------
extern "C" void kernel_launch(void* const* d_in, const int* in_sizes, int n_in,
                              void* d_out, int out_size) {
    (void)in_sizes; (void)n_in; (void)out_size;
    const float* query = (const float*)d_in[0];
    const float* value = (const float*)d_in[1];
    float* out = (float*)d_out;

    const int SMEM_BYTES = 2 * STAGE_BYTES;  // 192 KB
    static int attr_done = 0;
    if (!attr_done) {
        cudaFuncSetAttribute(gemm1_scores, cudaFuncAttributeMaxDynamicSharedMemorySize, SMEM_BYTES);
        cudaFuncSetAttribute(gemm2_out,    cudaFuncAttributeMaxDynamicSharedMemorySize, SMEM_BYTES);
        attr_done = 1;
    }

    rope_kernel<<<65536, 256>>>(query);

    dim3 gt(Dd / 32, Tt / 32, Hh);
    transpose_v<<<gt, 256>>>(value);

    dim3 g1(36, Hh);
    gemm1_scores<<<g1, 256, SMEM_BYTES>>>();

    dim3 g2(Dd / 128, Tt / 128, Hh);
    gemm2_out<<<g2, 256, SMEM_BYTES>>>(out);
}

// round 5
// speedup vs baseline: 6.9689x; 1.4820x over previous
#include <cuda_runtime.h>
#include <cuda_fp16.h>
#include <cstdint>
#include <math.h>

#define Hh 4
#define Tt 1024
#define Dd 8192
#define SCALE 0.011048543456039806f  /* 1/sqrt(8192) */

// ---------------- scratch (static device arrays; no allocation) -------------
__device__ __half g_qh[(size_t)Hh * Tt * Dd];   // 64 MB  rope'd query fp16
__device__ __half g_vt[(size_t)Hh * Dd * Tt];   // 64 MB  V^T [h][d][s] fp16
__device__ __half g_sh[(size_t)Hh * Tt * Tt];   // 8 MB   masked scores fp16

// ---------------- helpers (base-arch PTX only: cp.async/ldmatrix/mma.sync) --
__device__ __forceinline__ uint32_t smem_u32(const void* p) {
    uint32_t a;
    asm("{ .reg .u64 t; cvta.to.shared.u64 t, %1; cvt.u32.u64 %0, t; }" : "=r"(a) : "l"(p));
    return a;
}
__device__ __forceinline__ void cp16(uint32_t dst, const void* src) {
    asm volatile("cp.async.cg.shared.global [%0], [%1], 16;" :: "r"(dst), "l"(src) : "memory");
}
#define CP_COMMIT asm volatile("cp.async.commit_group;" ::: "memory")
#define CP_WAIT2  asm volatile("cp.async.wait_group 2;" ::: "memory")

__device__ __forceinline__ void ldsm4(uint32_t& r0, uint32_t& r1, uint32_t& r2, uint32_t& r3,
                                      uint32_t a) {
    asm volatile("ldmatrix.sync.aligned.m8n8.x4.shared.b16 {%0,%1,%2,%3}, [%4];"
                 : "=r"(r0), "=r"(r1), "=r"(r2), "=r"(r3) : "r"(a));
}
__device__ __forceinline__ void mma16816(float* c,
                                         uint32_t a0, uint32_t a1, uint32_t a2, uint32_t a3,
                                         uint32_t b0, uint32_t b1) {
    asm volatile(
        "mma.sync.aligned.m16n8k16.row.col.f32.f16.f16.f32 "
        "{%0,%1,%2,%3},{%4,%5,%6,%7},{%8,%9},{%0,%1,%2,%3};"
        : "+f"(c[0]), "+f"(c[1]), "+f"(c[2]), "+f"(c[3])
        : "r"(a0), "r"(a1), "r"(a2), "r"(a3), "r"(b0), "r"(b1));
}

// 128B rows (64 halves of K per sub-tile), XOR swizzle: conflict-free
#define SWZ(row, cb) ((row) * 128 + ((cb) ^ (((row) & 7) << 4)))

// BK = 128: each operand tile = 2 sub-tiles of [128 rows x 128B] = 32 KB
#define SUB_BYTES   16384
#define OPER_BYTES  32768
#define STAGE_BYTES 65536   /* A | B */
#define NSTAGE      3

// ---------------------------------------------------------------------------
// Kernel 1: bug-faithful ROPE -> fp16
// ---------------------------------------------------------------------------
__global__ void rope_kernel(const float* __restrict__ q) {
    long idx = (long)blockIdx.x * 256 + threadIdx.x;   // pair index
    int m   = (int)(idx & (Dd / 2 - 1));
    int row = (int)(idx >> 12);
    int t = row & (Tt - 1);
    int h = row >> 10;

    const float* qrow = q + ((long)row << 13);
    float v0 = qrow[2 * m];
    float v1 = qrow[2 * m + 1];

    int q2   = t & 1;
    int dsrc = (q2 << 12) + m;
    int tsrc = ((h & 1) << 9) + (t >> 1);
    int h2   = h >> 1;
    const float* base = q + ((long)(2 * h2) << 23);
    float rot0 = -base[(1L << 23) + (long)tsrc * Dd + dsrc];
    float rot1 =  base[(long)tsrc * Dd + dsrc];

    float freq = exp2f(-(float)m * (1.0f / 256.0f)) * 0.15915494309189535f;
    float ph = fmodf((float)t * freq, 1.0f);
    float c = cospif(2.0f * ph);
    float s = sinpif(2.0f * ph);

    float o0 = v0 * c + rot0 * s;
    float o1 = v1 * c + rot1 * s;

    long off = ((long)row << 13) + 2 * m;
    *(__half2*)(g_qh + off) = __halves2half2(__float2half_rn(o0), __float2half_rn(o1));
}

// ---------------------------------------------------------------------------
// Kernel 2: V transpose [h][s][d] fp32 -> V^T [h][d][s] fp16
// ---------------------------------------------------------------------------
__global__ __launch_bounds__(256) void transpose_v(const float* __restrict__ V) {
    __shared__ float tile[32][33];
    int h = blockIdx.z;
    int d0 = blockIdx.x * 32, s0 = blockIdx.y * 32;
    int lx = threadIdx.x & 31, ly = threadIdx.x >> 5;
    const float* src = V + ((long)h << 23);
#pragma unroll
    for (int r = 0; r < 4; r++)
        tile[ly + r * 8][lx] = src[(long)(s0 + ly + r * 8) * Dd + d0 + lx];
    __syncthreads();
    long ob = ((long)h << 23);
#pragma unroll
    for (int r = 0; r < 4; r++) {
        int d = d0 + ly + r * 8;
        g_vt[ob + (long)d * Tt + s0 + lx] = __float2half_rn(tile[lx][ly + r * 8]);
    }
}

// ---------------------------------------------------------------------------
// GEMM core: CTA tile 128x128, BK=128, 8 warps of 32x64, pure fp16 HMMA,
// fp32 accumulate, 3-stage cp.async ring.
// ---------------------------------------------------------------------------
__device__ __forceinline__ void ld_tile128(uint32_t sbase, const __half* g, long ld, int tid) {
#pragma unroll
    for (int i = 0; i < 8; i++) {
        int cid = i * 256 + tid;            // 0..2047
        int row = cid >> 4;
        int seg = cid & 15;                 // 16B segment within 256B row
        uint32_t off = (seg >> 3) * SUB_BYTES + SWZ(row, (seg & 7) << 4);
        cp16(sbase + off, g + (long)row * ld + seg * 8);
    }
}

__device__ __forceinline__ void gemm_run(
    const __half* __restrict__ A, long lda,
    const __half* __restrict__ B, long ldb,
    int nch, uint32_t s0, int tid, float acc[2][8][4], bool mma_on)
{
    const int lane = tid & 31, wid = tid >> 5;
    const int wm = (wid & 3) * 32, wn = (wid >> 2) * 64;

    // prologue: fill up to 3 stages
#pragma unroll
    for (int s = 0; s < NSTAGE; s++) {
        if (s < nch) {
            uint32_t sb = s0 + s * STAGE_BYTES;
            ld_tile128(sb,              A + s * 128, lda, tid);
            ld_tile128(sb + OPER_BYTES, B + s * 128, ldb, tid);
        }
        CP_COMMIT;
    }

    const int arow = lane & 15;
    const int acb  = (lane >> 4) << 4;
    const int brow = (lane & 7) + ((lane >> 4) << 3);
    const int bcb  = ((lane >> 3) & 1) << 4;

    int st = 0;
    for (int kc = 0; kc < nch; kc++) {
        CP_WAIT2;
        __syncthreads();
        uint32_t sb = s0 + st * STAGE_BYTES;
        if (mma_on) {
#pragma unroll
            for (int kb = 0; kb < 8; kb++) {
                uint32_t sub = (kb >> 2) * SUB_BYTES;
                int cbk = (kb & 3) * 32;
                uint32_t a[2][4];
#pragma unroll
                for (int mb = 0; mb < 2; mb++) {
                    int r = wm + mb * 16 + arow;
                    ldsm4(a[mb][0], a[mb][1], a[mb][2], a[mb][3],
                          sb + sub + SWZ(r, cbk + acb));
                }
#pragma unroll
                for (int nb = 0; nb < 4; nb++) {
                    int r = wn + nb * 16 + brow;
                    uint32_t b0, b1, b2, b3;
                    ldsm4(b0, b1, b2, b3, sb + OPER_BYTES + sub + SWZ(r, cbk + bcb));
#pragma unroll
                    for (int mb = 0; mb < 2; mb++) {
                        mma16816(acc[mb][2 * nb],     a[mb][0], a[mb][1], a[mb][2], a[mb][3], b0, b1);
                        mma16816(acc[mb][2 * nb + 1], a[mb][0], a[mb][1], a[mb][2], a[mb][3], b2, b3);
                    }
                }
            }
        }
        __syncthreads();
        if (kc + NSTAGE < nch) {
            uint32_t sb2 = s0 + st * STAGE_BYTES;
            ld_tile128(sb2,              A + (kc + NSTAGE) * 128, lda, tid);
            ld_tile128(sb2 + OPER_BYTES, B + (kc + NSTAGE) * 128, ldb, tid);
        }
        CP_COMMIT;
        st = (st == NSTAGE - 1) ? 0 : st + 1;
    }
}

// ---------------------------------------------------------------------------
// Kernel 3: scores = mask_strict_lower(Qr Qr^T) * SCALE  (lower-tri tiles only)
// ---------------------------------------------------------------------------
__global__ __launch_bounds__(256, 1) void gemm1_scores() {
    extern __shared__ char dyn[];
    uint32_t s0 = smem_u32(dyn);
    int tid = threadIdx.x;
    int h = blockIdx.y;
    int p = blockIdx.x;
    int bi = 0;
    while ((bi + 1) * (bi + 2) / 2 <= p) ++bi;
    int bj = p - bi * (bi + 1) / 2;

    long qb = ((long)h << 23);
    const __half* A = g_qh + qb + (long)bi * 128 * Dd;
    const __half* B = g_qh + qb + (long)bj * 128 * Dd;

    float acc[2][8][4];
#pragma unroll
    for (int a = 0; a < 2; a++)
#pragma unroll
        for (int b = 0; b < 8; b++)
#pragma unroll
            for (int c = 0; c < 4; c++) acc[a][b][c] = 0.f;

    const int lane = tid & 31, wid = tid >> 5;
    const int wm = (wid & 3) * 32, wn = (wid >> 2) * 64;
    // warp sub-tile fully masked on diagonal tiles when all s-cols >= all t-rows
    bool mma_on = !(bi == bj && wn >= wm + 32);

    gemm_run(A, Dd, B, Dd, Dd / 128, s0, tid, acc, mma_on);

    int tr0 = bi * 128 + wm + (lane >> 2);
    int sc0 = bj * 128 + wn + (lane & 3) * 2;
    long hb = (long)h * Tt * Tt;
#pragma unroll
    for (int mb = 0; mb < 2; mb++) {
#pragma unroll
        for (int n8 = 0; n8 < 8; n8++) {
            int sc = sc0 + n8 * 8;
            float* c = acc[mb][n8];
#pragma unroll
            for (int rh = 0; rh < 2; rh++) {
                int rr = tr0 + mb * 16 + rh * 8;
                float v0 = (sc     < rr) ? c[rh * 2 + 0] * SCALE : 0.f;
                float v1 = (sc + 1 < rr) ? c[rh * 2 + 1] * SCALE : 0.f;
                *(__half2*)(g_sh + hb + (long)rr * Tt + sc) =
                    __halves2half2(__float2half_rn(v0), __float2half_rn(v1));
            }
        }
    }
}

// ---------------------------------------------------------------------------
// Kernel 4: out = scores @ V   (A = scores fp16, B = V^T fp16), causal K
// ---------------------------------------------------------------------------
__global__ __launch_bounds__(256, 1) void gemm2_out(float* __restrict__ O) {
    extern __shared__ char dyn[];
    uint32_t s0 = smem_u32(dyn);
    int tid = threadIdx.x;
    int bn = blockIdx.x;          // d tile 0..63
    int bi = 7 - blockIdx.y;      // t tile, big-K first
    int h  = blockIdx.z;

    const __half* A = g_sh + (long)h * Tt * Tt + (long)bi * 128 * Tt;
    const __half* B = g_vt + ((long)h << 23) + (long)bn * 128 * Tt;

    float acc[2][8][4];
#pragma unroll
    for (int a = 0; a < 2; a++)
#pragma unroll
        for (int b = 0; b < 8; b++)
#pragma unroll
            for (int c = 0; c < 4; c++) acc[a][b][c] = 0.f;

    int nch = bi + 1;   // K = (bi+1)*128, chunks of 128
    gemm_run(A, Tt, B, Tt, nch, s0, tid, acc, true);

    const int lane = tid & 31, wid = tid >> 5;
    const int wm = (wid & 3) * 32, wn = (wid >> 2) * 64;
    int tr0 = bi * 128 + wm + (lane >> 2);
    int dc0 = bn * 128 + wn + (lane & 3) * 2;
    long hb = ((long)h << 23);
#pragma unroll
    for (int mb = 0; mb < 2; mb++) {
#pragma unroll
        for (int n8 = 0; n8 < 8; n8++) {
            int dc = dc0 + n8 * 8;
            float* c = acc[mb][n8];
#pragma unroll
            for (int rh = 0; rh < 2; rh++) {
                int rr = tr0 + mb * 16 + rh * 8;
                *(float2*)(O + hb + (long)rr * Dd + dc) =
                    make_float2(c[rh * 2 + 0], c[rh * 2 + 1]);
            }
        }
    }
}

// ---------------------------------------------------------------------------
extern "C" void kernel_launch(void* const* d_in, const int* in_sizes, int n_in,
                              void* d_out, int out_size) {
    (void)in_sizes; (void)n_in; (void)out_size;
    const float* query = (const float*)d_in[0];
    const float* value = (const float*)d_in[1];
    float* out = (float*)d_out;

    const int SMEM_BYTES = NSTAGE * STAGE_BYTES;  // 192 KB
    static int attr_done = 0;
    if (!attr_done) {
        cudaFuncSetAttribute(gemm1_scores, cudaFuncAttributeMaxDynamicSharedMemorySize, SMEM_BYTES);
        cudaFuncSetAttribute(gemm2_out,    cudaFuncAttributeMaxDynamicSharedMemorySize, SMEM_BYTES);
        attr_done = 1;
    }

    rope_kernel<<<65536, 256>>>(query);

    dim3 gt(Dd / 32, Tt / 32, Hh);
    transpose_v<<<gt, 256>>>(value);

    dim3 g1(36, Hh);
    gemm1_scores<<<g1, 256, SMEM_BYTES>>>();

    dim3 g2(Dd / 128, Tt / 128, Hh);
    gemm2_out<<<g2, 256, SMEM_BYTES>>>(out);
}